// round 1
// baseline (speedup 1.0000x reference)
#include <cuda_runtime.h>
#include <cuda_bf16.h>

// Problem constants (from reference): B=262144, G=25, KIN=15, KOUT=3
// x: (B, 375) f32 ; W: (25,3,15) f32 ; k_idx: (25,15) i32 ; v_idx: (25,3) i32
// out: (B, 75) f32
//
// Pure HBM-streaming kernel. Stage a contiguous 32-row tile of x in SMEM with
// float4 coalesced loads; each thread owns one group g (threadIdx.x), caches
// W[g], k_idx[g], v_idx[g] in registers once per block, then sweeps rows.

static constexpr int G      = 25;
static constexpr int KIN    = 15;
static constexpr int KOUT   = 3;
static constexpr int ROW_F  = G * KIN;    // 375 floats per x row
static constexpr int OUT_F  = G * KOUT;   // 75 floats per out row
static constexpr int W_N    = G * KOUT * KIN; // 1125
static constexpr int ROWS   = 32;         // rows per block
static constexpr int TY     = 10;
static constexpr int NTHR   = G * TY;     // 250 threads

__global__ void __launch_bounds__(256)
mlp_rsna4_kernel(const float* __restrict__ x,
                 const float* __restrict__ W,
                 const int*   __restrict__ kidx,
                 const int*   __restrict__ vidx,
                 float*       __restrict__ out,
                 int B)
{
    extern __shared__ float smem[];
    float* sx   = smem;                      // ROWS*ROW_F = 12000 floats
    float* sW   = smem + ROWS * ROW_F;       // 1125 floats
    int*   skid = (int*)(sW + W_N);          // 375 ints
    int*   svid = skid + ROW_F;              // 75 ints

    const int tid = threadIdx.y * G + threadIdx.x;
    const long long row0 = (long long)blockIdx.x * ROWS;

    // ---- Stage x tile (contiguous region, perfectly coalesced float4) ----
    {
        const float4* gx4 = reinterpret_cast<const float4*>(x + row0 * ROW_F);
        float4* sx4 = reinterpret_cast<float4*>(sx);
        constexpr int NF4 = ROWS * ROW_F / 4;   // 3000, and 3000 % 250 == 0
        #pragma unroll
        for (int j = 0; j < NF4; j += NTHR)
            sx4[j + tid] = gx4[j + tid];
    }
    // ---- Stage W and index tables ----
    for (int j = tid; j < W_N; j += NTHR)   sW[j]   = W[j];
    for (int j = tid; j < ROW_F; j += NTHR) skid[j] = kidx[j];
    if (tid < OUT_F)                        svid[tid] = vidx[tid];
    __syncthreads();

    // ---- Per-thread: fixed group g; cache W/k_idx/v_idx in registers ----
    const int g = threadIdx.x;
    float w[KOUT][KIN];
    #pragma unroll
    for (int o = 0; o < KOUT; o++)
        #pragma unroll
        for (int i = 0; i < KIN; i++)
            w[o][i] = sW[(g * KOUT + o) * KIN + i];

    int kid[KIN];
    #pragma unroll
    for (int i = 0; i < KIN; i++) kid[i] = skid[g * KIN + i];

    int vo[KOUT];
    #pragma unroll
    for (int o = 0; o < KOUT; o++) vo[o] = svid[g * KOUT + o];

    // ---- Sweep rows of the tile ----
    for (int r = threadIdx.y; r < ROWS; r += TY) {
        const long long grow = row0 + r;
        if (grow >= B) break;
        const float* xr = sx + r * ROW_F;
        float acc0 = 0.f, acc1 = 0.f, acc2 = 0.f;
        #pragma unroll
        for (int i = 0; i < KIN; i++) {
            float xv = xr[kid[i]];
            acc0 = fmaf(xv, w[0][i], acc0);
            acc1 = fmaf(xv, w[1][i], acc1);
            acc2 = fmaf(xv, w[2][i], acc2);
        }
        float* orow = out + grow * OUT_F;
        orow[vo[0]] = acc0;
        orow[vo[1]] = acc1;
        orow[vo[2]] = acc2;
    }
}

extern "C" void kernel_launch(void* const* d_in, const int* in_sizes, int n_in,
                              void* d_out, int out_size)
{
    const float* x    = (const float*)d_in[0];
    const float* W    = (const float*)d_in[1];
    const int*   kidx = (const int*)d_in[2];
    const int*   vidx = (const int*)d_in[3];
    float*       out  = (float*)d_out;

    const int B = in_sizes[0] / ROW_F;

    const size_t smem_bytes = (size_t)(ROWS * ROW_F + W_N) * sizeof(float)
                            + (size_t)(ROW_F + OUT_F) * sizeof(int);   // 54300 B

    cudaFuncSetAttribute(mlp_rsna4_kernel,
                         cudaFuncAttributeMaxDynamicSharedMemorySize,
                         (int)smem_bytes);

    dim3 blk(G, TY);                     // (25, 10) = 250 threads
    int grid = (B + ROWS - 1) / ROWS;    // 8192 for B=262144
    mlp_rsna4_kernel<<<grid, blk, smem_bytes>>>(x, W, kidx, vidx, out, B);
}

// round 2
// speedup vs baseline: 1.1825x; 1.1825x over previous
#include <cuda_runtime.h>
#include <cuda_bf16.h>

// B=262144, G=25, KIN=15, KOUT=3
// x: (B,375) f32 ; W: (25,3,15) f32 ; k_idx: (25,15) i32 ; v_idx: (25,3) i32
// out: (B,75) f32
//
// Thread layout: one thread per output element p = g*3+o (75 of them) x 4 row
// slots = 300 threads. Each thread caches W[g,o,:] (15f) and k_idx[g,:] (15i)
// in registers ONCE (persistent grid-stride over tiles), computes 4 rows per
// tile via broadcast-friendly LDS, scatters through v_idx into a smem out
// tile, and the block stores the out tile with coalesced float4.

static constexpr int G     = 25;
static constexpr int KIN   = 15;
static constexpr int KOUT  = 3;
static constexpr int ROW_F = G * KIN;   // 375
static constexpr int OUT_F = G * KOUT;  // 75
static constexpr int ROWS  = 16;        // rows per tile
static constexpr int SLOTS = 4;         // row slots
static constexpr int NT    = OUT_F * SLOTS;  // 300 threads
static constexpr int RPT   = ROWS / SLOTS;   // 4 rows per thread
static constexpr int X4_PER_TILE = ROWS * ROW_F / 4;  // 1500
static constexpr int X4_PER_THR  = X4_PER_TILE / NT;  // 5

__global__ void __launch_bounds__(NT, 4)
mlp_rsna4_kernel(const float* __restrict__ x,
                 const float* __restrict__ W,
                 const int*   __restrict__ kidx,
                 const int*   __restrict__ vidx,
                 float*       __restrict__ out,
                 int B, int ntiles)
{
    __shared__ float sx[ROWS * ROW_F];    // 24000 B
    __shared__ float sout[ROWS * OUT_F];  //  4800 B

    const int tid  = threadIdx.x;
    const int p    = tid % OUT_F;   // output element 0..74
    const int slot = tid / OUT_F;   // 0..3
    const int g    = p / KOUT;
    const int o    = p % KOUT;

    // Per-thread constants, loaded once per block (L1/L2-hot).
    float w[KIN];
    int   kid[KIN];
    #pragma unroll
    for (int i = 0; i < KIN; i++) {
        w[i]   = __ldg(&W[(g * KOUT + o) * KIN + i]);
        kid[i] = __ldg(&kidx[g * KIN + i]);
    }
    const int vo = __ldg(&vidx[p]);   // scatter position within 75-wide row

    float4*       sx4 = reinterpret_cast<float4*>(sx);
    float4*       so4 = reinterpret_cast<float4*>(sout);

    for (int tile = blockIdx.x; tile < ntiles; tile += gridDim.x) {
        const long long row0 = (long long)tile * ROWS;
        const bool full = (row0 + ROWS) <= (long long)B;

        __syncthreads();   // prev tile's sout stores + sx reads complete

        // ---- Stage x tile: contiguous, coalesced float4 ----
        const float4* gx4 = reinterpret_cast<const float4*>(x + row0 * ROW_F);
        if (full) {
            #pragma unroll
            for (int k = 0; k < X4_PER_THR; k++)
                sx4[tid + k * NT] = gx4[tid + k * NT];
        } else {
            const long long lim4 = ((long long)B * ROW_F - row0 * ROW_F) / 4;
            #pragma unroll
            for (int k = 0; k < X4_PER_THR; k++) {
                int j = tid + k * NT;
                sx4[j] = (j < lim4) ? gx4[j] : make_float4(0.f, 0.f, 0.f, 0.f);
            }
        }
        so4[tid] = make_float4(0.f, 0.f, 0.f, 0.f);   // zero out-tile (scatter may not cover)
        __syncthreads();

        // ---- Compute: 4 independent rows per thread for ILP ----
        float acc[RPT];
        #pragma unroll
        for (int rr = 0; rr < RPT; rr++) acc[rr] = 0.f;

        #pragma unroll
        for (int i = 0; i < KIN; i++) {
            const int c = kid[i];
            const float wi = w[i];
            #pragma unroll
            for (int rr = 0; rr < RPT; rr++) {
                const int r = rr * SLOTS + slot;
                acc[rr] = fmaf(sx[r * ROW_F + c], wi, acc[rr]);
            }
        }

        #pragma unroll
        for (int rr = 0; rr < RPT; rr++) {
            const int r = rr * SLOTS + slot;
            sout[r * OUT_F + vo] = acc[rr];
        }
        __syncthreads();

        // ---- Store out tile: coalesced float4 (1 per thread) ----
        float4* go4 = reinterpret_cast<float4*>(out + row0 * OUT_F);
        if (full) {
            go4[tid] = so4[tid];
        } else {
            const long long lim4 = ((long long)B * OUT_F - row0 * OUT_F) / 4;
            if (tid < lim4) go4[tid] = so4[tid];
        }
    }
}

extern "C" void kernel_launch(void* const* d_in, const int* in_sizes, int n_in,
                              void* d_out, int out_size)
{
    const float* x    = (const float*)d_in[0];
    const float* W    = (const float*)d_in[1];
    const int*   kidx = (const int*)d_in[2];
    const int*   vidx = (const int*)d_in[3];
    float*       out  = (float*)d_out;

    const int B = in_sizes[0] / ROW_F;
    const int ntiles = (B + ROWS - 1) / ROWS;   // 16384 for B=262144

    int grid = 2048;
    if (grid > ntiles) grid = ntiles;

    mlp_rsna4_kernel<<<grid, NT>>>(x, W, kidx, vidx, out, B, ntiles);
}